// round 8
// baseline (speedup 1.0000x reference)
#include <cuda_runtime.h>
#include <cuda_bf16.h>
#include <cstdint>

// ---------------------------------------------------------------------------
// MiddleLayerDecoder — round 5: activations pre-split to bf16 hi/lo planes,
// cp.async 4-stage pipelined HMMA GEMMs (mma.sync m16n8k16, 3-term split).
// ---------------------------------------------------------------------------

#define N_NODES 50000
#define KPTS 8
#define M_PTS (N_NODES * KPTS)

// ---- activation planes (bf16 hi/lo) ----
__device__ __align__(16) __nv_bfloat16 g_xhi[(size_t)N_NODES * 256];
__device__ __align__(16) __nv_bfloat16 g_xlo[(size_t)N_NODES * 256];
__device__ __align__(16) __nv_bfloat16 g_h1hi[(size_t)N_NODES * 256];
__device__ __align__(16) __nv_bfloat16 g_h1lo[(size_t)N_NODES * 256];
__device__ __align__(16) __nv_bfloat16 g_h2hi[(size_t)N_NODES * 128];
__device__ __align__(16) __nv_bfloat16 g_h2lo[(size_t)N_NODES * 128];
__device__ __align__(16) __nv_bfloat16 g_fhi[(size_t)N_NODES * 64];
__device__ __align__(16) __nv_bfloat16 g_flo[(size_t)N_NODES * 64];
__device__ __align__(16) __nv_bfloat16 g_h0hi[(size_t)M_PTS * 256];
__device__ __align__(16) __nv_bfloat16 g_h0lo[(size_t)M_PTS * 256];
__device__ __align__(16) __nv_bfloat16 g_p1hi[(size_t)M_PTS * 256];
__device__ __align__(16) __nv_bfloat16 g_p1lo[(size_t)M_PTS * 256];
// fp32 scratch
__device__ float g_T[(size_t)N_NODES * 256];
__device__ float g_A[(size_t)N_NODES * 256];
// weight planes [Kp][Np]
__device__ __align__(16) __nv_bfloat16 g_whi[335872];
__device__ __align__(16) __nv_bfloat16 g_wlo[335872];

#define OFF_WG0  0
#define OFF_WG1  65536
#define OFF_WG2  98304
#define OFF_WDEC 114688
#define OFF_W0A  122880
#define OFF_W0B  188416
#define OFF_W1   204800
#define OFF_W2   270336

__device__ __forceinline__ uint32_t smem_u32(const void* p) {
    uint32_t a;
    asm("{ .reg .u64 t; cvta.to.shared.u64 t, %1; cvt.u32.u64 %0, t; }" : "=r"(a) : "l"(p));
    return a;
}
__device__ __forceinline__ uint32_t pack2(__nv_bfloat16 a, __nv_bfloat16 b) {
    return (uint32_t)__bfloat16_as_ushort(a) | ((uint32_t)__bfloat16_as_ushort(b) << 16);
}
__device__ __forceinline__ void ldm_x4(uint32_t* r, uint32_t addr) {
    asm volatile("ldmatrix.sync.aligned.m8n8.x4.shared.b16 {%0,%1,%2,%3}, [%4];"
                 : "=r"(r[0]), "=r"(r[1]), "=r"(r[2]), "=r"(r[3]) : "r"(addr));
}
__device__ __forceinline__ void ldm_x4t(uint32_t* r, uint32_t addr) {
    asm volatile("ldmatrix.sync.aligned.m8n8.x4.trans.shared.b16 {%0,%1,%2,%3}, [%4];"
                 : "=r"(r[0]), "=r"(r[1]), "=r"(r[2]), "=r"(r[3]) : "r"(addr));
}
__device__ __forceinline__ void mma16816(float* c, const uint32_t* a, const uint32_t* b) {
    asm volatile("mma.sync.aligned.m16n8k16.row.col.f32.bf16.bf16.f32 "
                 "{%0,%1,%2,%3}, {%4,%5,%6,%7}, {%8,%9}, {%0,%1,%2,%3};"
                 : "+f"(c[0]), "+f"(c[1]), "+f"(c[2]), "+f"(c[3])
                 : "r"(a[0]), "r"(a[1]), "r"(a[2]), "r"(a[3]), "r"(b[0]), "r"(b[1]));
}
__device__ __forceinline__ void cp16(uint32_t dst, const void* src, int sz) {
    asm volatile("cp.async.cg.shared.global [%0], [%1], 16, %2;"
                 :: "r"(dst), "l"(src), "r"(sz) : "memory");
}
__device__ __forceinline__ void cp_commit() {
    asm volatile("cp.async.commit_group;" ::: "memory");
}
__device__ __forceinline__ void cp_wait2() {
    asm volatile("cp.async.wait_group 2;" ::: "memory");
}

// ---------------------------------------------------------------------------
// SMEM stage layout: A planes 128x(64B data,80B stride); B planes 32x(256B,272B)
// ---------------------------------------------------------------------------
#define ASTRIDE 80
#define BSTRIDE 272
#define SA_HI 0
#define SA_LO 10240
#define SB_HI 20480
#define SB_LO 29184
#define STAGE_BYTES 37888
#define STAGES 4
#define SMEM_DYN (STAGE_BYTES * STAGES)

__global__ __launch_bounds__(256, 1)
void gemm_mma(const __nv_bfloat16* __restrict__ Ahi,
              const __nv_bfloat16* __restrict__ Alo,
              const __nv_bfloat16* __restrict__ Bhi,
              const __nv_bfloat16* __restrict__ Blo,
              const float* __restrict__ bias, const float* __restrict__ Cin,
              float* __restrict__ OutF,
              __nv_bfloat16* __restrict__ OutHi, __nv_bfloat16* __restrict__ OutLo,
              int M, int K, int Np, int realN, int ldc, int doRelu)
{
    extern __shared__ __align__(128) char smem[];
    const uint32_t sb = smem_u32(smem);
    const int tid = threadIdx.x, lane = tid & 31, wid = tid >> 5;
    const int warpM = (wid & 1) * 64;
    const int warpN = (wid >> 1) * 32;
    const long m0 = (long)blockIdx.y * 128;
    const int  n0 = blockIdx.x * 128;
    const int  nc = K >> 5;

    // cp.async issue for one K32 chunk into its stage
    auto issue_chunk = [&](int c) {
        const uint32_t st = sb + (uint32_t)(c & (STAGES - 1)) * STAGE_BYTES;
        const int k0 = c << 5;
        // A planes: 2 x 512 granules (16B = 8 bf16)
#pragma unroll
        for (int t = 0; t < 4; t++) {
            const int gi = tid + t * 256;
            const int pl = gi >> 9, idx = gi & 511;
            const int row = idx >> 2, q = idx & 3;
            const long gm = m0 + row;
            const __nv_bfloat16* src =
                (pl ? Alo : Ahi) + (gm < M ? gm : 0) * (long)K + k0 + q * 8;
            const uint32_t dst = st + (pl ? SA_LO : SA_HI) + row * ASTRIDE + q * 16;
            cp16(dst, src, gm < M ? 16 : 0);
        }
        // B planes: 2 x 512 granules
#pragma unroll
        for (int t = 0; t < 4; t++) {
            const int gi = tid + t * 256;
            const int pl = gi >> 9, idx = gi & 511;
            const int row = idx >> 4, q = idx & 15;
            const __nv_bfloat16* src =
                (pl ? Blo : Bhi) + (long)(k0 + row) * Np + n0 + q * 8;
            const uint32_t dst = st + (pl ? SB_LO : SB_HI) + row * BSTRIDE + q * 16;
            cp16(dst, src, 16);
        }
    };

    float acc[4][4][4];
#pragma unroll
    for (int i = 0; i < 4; i++)
#pragma unroll
        for (int j = 0; j < 4; j++)
#pragma unroll
            for (int r = 0; r < 4; r++) acc[i][j][r] = 0.f;

    const uint32_t aOff = (uint32_t)((warpM + (lane & 15)) * ASTRIDE + ((lane >> 4) << 4));
    const uint32_t bOff = (uint32_t)(((lane & 7) + ((lane >> 3) & 1) * 8) * BSTRIDE +
                                     (warpN + ((lane >> 4) << 3)) * 2);

    // prologue: STAGES-1 committed groups
#pragma unroll
    for (int t = 0; t < STAGES - 1; t++) {
        if (t < nc) issue_chunk(t);
        cp_commit();
    }

    for (int c = 0; c < nc; c++) {
        cp_wait2();
        __syncthreads();

        if (c + STAGES - 1 < nc) issue_chunk(c + STAGES - 1);
        cp_commit();

        const uint32_t st = sb + (uint32_t)(c & (STAGES - 1)) * STAGE_BYTES;
        const uint32_t aAddr = st + aOff;
        const uint32_t bAddr = st + SB_HI + bOff;

#pragma unroll
        for (int ks = 0; ks < 2; ks++) {
            uint32_t ah[4][4], al[4][4], bh[8], bl[8];
#pragma unroll
            for (int mi = 0; mi < 4; mi++) {
                const uint32_t ao = aAddr + (uint32_t)(mi * 16 * ASTRIDE + ks * 32);
                ldm_x4(ah[mi], ao + SA_HI);
                ldm_x4(al[mi], ao + SA_LO);
            }
#pragma unroll
            for (int j = 0; j < 2; j++) {
                const uint32_t bo = bAddr + (uint32_t)(ks * 16 * BSTRIDE + j * 32);
                ldm_x4t(bh + j * 4, bo);
                ldm_x4t(bl + j * 4, bo + (SB_LO - SB_HI));
            }
#pragma unroll
            for (int mi = 0; mi < 4; mi++)
#pragma unroll
                for (int nj = 0; nj < 4; nj++) {
                    mma16816(acc[mi][nj], ah[mi], bh + nj * 2);
                    mma16816(acc[mi][nj], ah[mi], bl + nj * 2);
                    mma16816(acc[mi][nj], al[mi], bh + nj * 2);
                }
        }
        __syncthreads();
    }

    // ---- epilogue ----
    const long gmBase = m0 + warpM + (lane >> 2);
    const int  gcBase = n0 + warpN + (lane & 3) * 2;
#pragma unroll
    for (int mi = 0; mi < 4; mi++) {
#pragma unroll
        for (int half = 0; half < 2; half++) {
            const long gr = gmBase + mi * 16 + half * 8;
            if (gr >= M) continue;
#pragma unroll
            for (int nj = 0; nj < 4; nj++) {
                const int gc = gcBase + nj * 8;
                if (gc >= realN) continue;
                float vx = acc[mi][nj][half * 2 + 0];
                float vy = acc[mi][nj][half * 2 + 1];
                if (bias) { vx += bias[gc]; vy += bias[gc + 1]; }
                if (Cin) {
                    const float2 cv = *(const float2*)(Cin + gr * (long)ldc + gc);
                    vx += cv.x; vy += cv.y;
                }
                if (doRelu) { vx = fmaxf(vx, 0.f); vy = fmaxf(vy, 0.f); }
                if (OutHi) {
                    const __nv_bfloat16 hx = __float2bfloat16(vx);
                    const __nv_bfloat16 hy = __float2bfloat16(vy);
                    *(uint32_t*)(OutHi + gr * (long)ldc + gc) = pack2(hx, hy);
                    *(uint32_t*)(OutLo + gr * (long)ldc + gc) =
                        pack2(__float2bfloat16(vx - __bfloat162float(hx)),
                              __float2bfloat16(vy - __bfloat162float(hy)));
                } else {
                    float2 o; o.x = vx; o.y = vy;
                    *(float2*)(OutF + gr * (long)ldc + gc) = o;
                }
            }
        }
    }
}

// ---------------------------------------------------------------------------
// weight prep: W[K,N] fp32 -> bf16 hi/lo planes [Kp][Np]
// ---------------------------------------------------------------------------
__global__ __launch_bounds__(256)
void prep_weight(const float* __restrict__ W, __nv_bfloat16* __restrict__ hi,
                 __nv_bfloat16* __restrict__ lo, int K, int N, int Kpad, int Npad)
{
    const int i = blockIdx.x * blockDim.x + threadIdx.x;
    if (i >= Kpad * Npad) return;
    const int k = i / Npad, n = i % Npad;
    const float v = (k < K && n < N) ? W[(long)k * N + n] : 0.f;
    const __nv_bfloat16 h = __float2bfloat16(v);
    hi[i] = h;
    lo[i] = __float2bfloat16(v - __bfloat162float(h));
}

// split X fp32 -> hi/lo planes
__global__ __launch_bounds__(256)
void split_x(const float* __restrict__ X, __nv_bfloat16* __restrict__ hi,
             __nv_bfloat16* __restrict__ lo)
{
    const long i = (long)blockIdx.x * blockDim.x + threadIdx.x;  // per float4
    if (i >= (long)N_NODES * 64) return;
    const float4 v = *(const float4*)(X + i * 4);
    const __nv_bfloat16 hx = __float2bfloat16(v.x), hy = __float2bfloat16(v.y);
    const __nv_bfloat16 hz = __float2bfloat16(v.z), hw = __float2bfloat16(v.w);
    uint2 hp, lp;
    hp.x = pack2(hx, hy); hp.y = pack2(hz, hw);
    lp.x = pack2(__float2bfloat16(v.x - __bfloat162float(hx)),
                 __float2bfloat16(v.y - __bfloat162float(hy)));
    lp.y = pack2(__float2bfloat16(v.z - __bfloat162float(hz)),
                 __float2bfloat16(v.w - __bfloat162float(hw)));
    *(uint2*)(hi + i * 4) = hp;
    *(uint2*)(lo + i * 4) = lp;
}

// ---------------------------------------------------------------------------
// h0[p,j] = relu(A[p/8,j] + sum_t rel[p,t]*W0c[t,j])  -> hi/lo planes
// ---------------------------------------------------------------------------
__global__ __launch_bounds__(256)
void point_layer0(const float* __restrict__ A, const float* __restrict__ rel,
                  const float* __restrict__ W0c,
                  __nv_bfloat16* __restrict__ h0hi, __nv_bfloat16* __restrict__ h0lo)
{
    const long idx = (long)blockIdx.x * blockDim.x + threadIdx.x;
    if (idx >= (long)M_PTS * 64) return;
    const long p = idx >> 6;
    const int j4 = (int)(idx & 63) << 2;
    const long node = p >> 3;

    const float r0 = rel[p * 3 + 0], r1 = rel[p * 3 + 1], r2 = rel[p * 3 + 2];
    const float4 a  = *(const float4*)(A + node * 256 + j4);
    const float4 w0 = *(const float4*)(W0c + 0   + j4);
    const float4 w1 = *(const float4*)(W0c + 256 + j4);
    const float4 w2 = *(const float4*)(W0c + 512 + j4);
    float4 o;
    o.x = fmaxf(a.x + r0 * w0.x + r1 * w1.x + r2 * w2.x, 0.f);
    o.y = fmaxf(a.y + r0 * w0.y + r1 * w1.y + r2 * w2.y, 0.f);
    o.z = fmaxf(a.z + r0 * w0.z + r1 * w1.z + r2 * w2.z, 0.f);
    o.w = fmaxf(a.w + r0 * w0.w + r1 * w1.w + r2 * w2.w, 0.f);
    const __nv_bfloat16 hx = __float2bfloat16(o.x), hy = __float2bfloat16(o.y);
    const __nv_bfloat16 hz = __float2bfloat16(o.z), hw = __float2bfloat16(o.w);
    uint2 hp, lp;
    hp.x = pack2(hx, hy); hp.y = pack2(hz, hw);
    lp.x = pack2(__float2bfloat16(o.x - __bfloat162float(hx)),
                 __float2bfloat16(o.y - __bfloat162float(hy)));
    lp.y = pack2(__float2bfloat16(o.z - __bfloat162float(hz)),
                 __float2bfloat16(o.w - __bfloat162float(hw)));
    *(uint2*)(h0hi + p * 256 + j4) = hp;
    *(uint2*)(h0lo + p * 256 + j4) = lp;
}

__global__ __launch_bounds__(256)
void cluster_kernel(float* __restrict__ out)
{
    const int i = blockIdx.x * blockDim.x + threadIdx.x;
    if (i < M_PTS) out[i] = (float)(i >> 3);
}

// ---------------------------------------------------------------------------
// launch
// ---------------------------------------------------------------------------
extern "C" void kernel_launch(void* const* d_in, const int* in_sizes, int n_in,
                              void* d_out, int out_size)
{
    const float* X    = (const float*)d_in[0];
    const float* Wg0  = (const float*)d_in[1];
    const float* bg0  = (const float*)d_in[2];
    const float* Wg1  = (const float*)d_in[3];
    const float* bg1  = (const float*)d_in[4];
    const float* Wg2  = (const float*)d_in[5];
    const float* bg2  = (const float*)d_in[6];
    const float* Wdec = (const float*)d_in[7];
    const float* bdec = (const float*)d_in[8];
    const float* W0   = (const float*)d_in[9];
    const float* b0   = (const float*)d_in[10];
    const float* W1   = (const float*)d_in[11];
    const float* b1   = (const float*)d_in[12];
    const float* W2   = (const float*)d_in[13];
    const float* b2   = (const float*)d_in[14];

    float* out = (float*)d_out;
    float* out_rel     = out;
    float* out_decoded = out + 1200000;
    float* out_cluster = out + 1200000 + 102400000;

    float *T, *Abuf;
    __nv_bfloat16 *whi, *wlo, *xhi, *xlo, *h1hi, *h1lo, *h2hi, *h2lo;
    __nv_bfloat16 *fhi, *flo, *h0hi, *h0lo, *p1hi, *p1lo;
    cudaGetSymbolAddress((void**)&T,    g_T);
    cudaGetSymbolAddress((void**)&Abuf, g_A);
    cudaGetSymbolAddress((void**)&whi,  g_whi);
    cudaGetSymbolAddress((void**)&wlo,  g_wlo);
    cudaGetSymbolAddress((void**)&xhi,  g_xhi);
    cudaGetSymbolAddress((void**)&xlo,  g_xlo);
    cudaGetSymbolAddress((void**)&h1hi, g_h1hi);
    cudaGetSymbolAddress((void**)&h1lo, g_h1lo);
    cudaGetSymbolAddress((void**)&h2hi, g_h2hi);
    cudaGetSymbolAddress((void**)&h2lo, g_h2lo);
    cudaGetSymbolAddress((void**)&fhi,  g_fhi);
    cudaGetSymbolAddress((void**)&flo,  g_flo);
    cudaGetSymbolAddress((void**)&h0hi, g_h0hi);
    cudaGetSymbolAddress((void**)&h0lo, g_h0lo);
    cudaGetSymbolAddress((void**)&p1hi, g_p1hi);
    cudaGetSymbolAddress((void**)&p1lo, g_p1lo);

    cudaFuncSetAttribute(gemm_mma, cudaFuncAttributeMaxDynamicSharedMemorySize, SMEM_DYN);

    const float* W0a = W0;
    const float* W0b = W0 + 256 * 256;
    const float* W0c = W0 + 320 * 256;

    auto prep = [&](const float* W, int off, int K, int N, int Kp, int Np) {
        const int total = Kp * Np;
        prep_weight<<<(total + 255) / 256, 256>>>(W, whi + off, wlo + off, K, N, Kp, Np);
    };
    prep(Wg0,  OFF_WG0,  256, 256, 256, 256);
    prep(Wg1,  OFF_WG1,  256, 128, 256, 128);
    prep(Wg2,  OFF_WG2,  128,  64, 128, 128);
    prep(Wdec, OFF_WDEC,  64,  24,  64, 128);
    prep(W0a,  OFF_W0A,  256, 256, 256, 256);
    prep(W0b,  OFF_W0B,   64, 256,  64, 256);
    prep(W1,   OFF_W1,   256, 256, 256, 256);
    prep(W2,   OFF_W2,   256, 256, 256, 256);

    split_x<<<(N_NODES * 64 + 255) / 256, 256>>>(X, xhi, xlo);

    auto gemm = [&](const __nv_bfloat16* Ahi, const __nv_bfloat16* Alo, int off,
                    const float* bias, const float* Cin,
                    float* OutF, __nv_bfloat16* OutHi, __nv_bfloat16* OutLo,
                    int M, int K, int Np, int realN, int ldc, int relu) {
        dim3 grid((realN + 127) / 128, (M + 127) / 128);
        gemm_mma<<<grid, 256, SMEM_DYN>>>(Ahi, Alo, whi + off, wlo + off, bias, Cin,
                                          OutF, OutHi, OutLo, M, K, Np, realN, ldc, relu);
    };

    // global MLP
    gemm(xhi,  xlo,  OFF_WG0, bg0, nullptr, nullptr, h1hi, h1lo, N_NODES, 256, 256, 256, 256, 1);
    gemm(h1hi, h1lo, OFF_WG1, bg1, nullptr, nullptr, h2hi, h2lo, N_NODES, 256, 128, 128, 128, 1);
    gemm(h2hi, h2lo, OFF_WG2, bg2, nullptr, nullptr, fhi,  flo,  N_NODES, 128, 128,  64,  64, 1);
    // decoder head -> relative_points (fp32 into d_out)
    gemm(fhi, flo, OFF_WDEC, bdec, nullptr, out_rel, nullptr, nullptr, N_NODES, 64, 128, 24, 24, 0);
    // node-level shared part of point-MLP layer 0 (fp32)
    gemm(xhi, xlo, OFF_W0A, b0,      nullptr, T,    nullptr, nullptr, N_NODES, 256, 256, 256, 256, 0);
    gemm(fhi, flo, OFF_W0B, nullptr, T,       Abuf, nullptr, nullptr, N_NODES,  64, 256, 256, 256, 0);
    // per-point fold-in -> h0 planes
    {
        const long total = (long)M_PTS * 64;
        point_layer0<<<(int)((total + 255) / 256), 256>>>(Abuf, out_rel, W0c, h0hi, h0lo);
    }
    // point-MLP layers 1 & 2
    gemm(h0hi, h0lo, OFF_W1, b1, nullptr, nullptr,     p1hi, p1lo, M_PTS, 256, 256, 256, 256, 1);
    gemm(p1hi, p1lo, OFF_W2, b2, nullptr, out_decoded, nullptr, nullptr, M_PTS, 256, 256, 256, 256, 1);
    // cluster ids
    cluster_kernel<<<(M_PTS + 255) / 256, 256>>>(out_cluster);
}

// round 9
// speedup vs baseline: 1.2822x; 1.2822x over previous
#include <cuda_runtime.h>
#include <cuda_bf16.h>
#include <cstdint>

// ---------------------------------------------------------------------------
// MiddleLayerDecoder — round 8: 2 CTAs/SM (2-stage cp.async ring) +
// point_layer0 fused into the W1 GEMM's A-path (MODE 1).
// ---------------------------------------------------------------------------

#define N_NODES 50000
#define KPTS 8
#define M_PTS (N_NODES * KPTS)

// ---- activation planes (bf16 hi/lo) ----
__device__ __align__(16) __nv_bfloat16 g_xhi[(size_t)N_NODES * 256];
__device__ __align__(16) __nv_bfloat16 g_xlo[(size_t)N_NODES * 256];
__device__ __align__(16) __nv_bfloat16 g_h1hi[(size_t)N_NODES * 256];
__device__ __align__(16) __nv_bfloat16 g_h1lo[(size_t)N_NODES * 256];
__device__ __align__(16) __nv_bfloat16 g_h2hi[(size_t)N_NODES * 128];
__device__ __align__(16) __nv_bfloat16 g_h2lo[(size_t)N_NODES * 128];
__device__ __align__(16) __nv_bfloat16 g_fhi[(size_t)N_NODES * 64];
__device__ __align__(16) __nv_bfloat16 g_flo[(size_t)N_NODES * 64];
__device__ __align__(16) __nv_bfloat16 g_p1hi[(size_t)M_PTS * 256];
__device__ __align__(16) __nv_bfloat16 g_p1lo[(size_t)M_PTS * 256];
// fp32 scratch
__device__ float g_T[(size_t)N_NODES * 256];
__device__ float g_A[(size_t)N_NODES * 256];
// weight planes [Kp][Np]
__device__ __align__(16) __nv_bfloat16 g_whi[335872];
__device__ __align__(16) __nv_bfloat16 g_wlo[335872];

#define OFF_WG0  0
#define OFF_WG1  65536
#define OFF_WG2  98304
#define OFF_WDEC 114688
#define OFF_W0A  122880
#define OFF_W0B  188416
#define OFF_W1   204800
#define OFF_W2   270336

__device__ __forceinline__ uint32_t smem_u32(const void* p) {
    uint32_t a;
    asm("{ .reg .u64 t; cvta.to.shared.u64 t, %1; cvt.u32.u64 %0, t; }" : "=r"(a) : "l"(p));
    return a;
}
__device__ __forceinline__ uint32_t pack2(__nv_bfloat16 a, __nv_bfloat16 b) {
    return (uint32_t)__bfloat16_as_ushort(a) | ((uint32_t)__bfloat16_as_ushort(b) << 16);
}
__device__ __forceinline__ void ldm_x4(uint32_t* r, uint32_t addr) {
    asm volatile("ldmatrix.sync.aligned.m8n8.x4.shared.b16 {%0,%1,%2,%3}, [%4];"
                 : "=r"(r[0]), "=r"(r[1]), "=r"(r[2]), "=r"(r[3]) : "r"(addr));
}
__device__ __forceinline__ void ldm_x4t(uint32_t* r, uint32_t addr) {
    asm volatile("ldmatrix.sync.aligned.m8n8.x4.trans.shared.b16 {%0,%1,%2,%3}, [%4];"
                 : "=r"(r[0]), "=r"(r[1]), "=r"(r[2]), "=r"(r[3]) : "r"(addr));
}
__device__ __forceinline__ void mma16816(float* c, const uint32_t* a, const uint32_t* b) {
    asm volatile("mma.sync.aligned.m16n8k16.row.col.f32.bf16.bf16.f32 "
                 "{%0,%1,%2,%3}, {%4,%5,%6,%7}, {%8,%9}, {%0,%1,%2,%3};"
                 : "+f"(c[0]), "+f"(c[1]), "+f"(c[2]), "+f"(c[3])
                 : "r"(a[0]), "r"(a[1]), "r"(a[2]), "r"(a[3]), "r"(b[0]), "r"(b[1]));
}
__device__ __forceinline__ void cp16(uint32_t dst, const void* src, int sz) {
    asm volatile("cp.async.cg.shared.global [%0], [%1], 16, %2;"
                 :: "r"(dst), "l"(src), "r"(sz) : "memory");
}
__device__ __forceinline__ void cp_commit() {
    asm volatile("cp.async.commit_group;" ::: "memory");
}
__device__ __forceinline__ void cp_wait1() {
    asm volatile("cp.async.wait_group 1;" ::: "memory");
}

// stage layout: A planes 128x(64B,80B stride); B planes 32x(256B,272B stride)
#define ASTRIDE 80
#define BSTRIDE 272
#define SA_HI 0
#define SA_LO 10240
#define SB_HI 20480
#define SB_LO 29184
#define STAGE_BYTES 37888
#define SMEM_DYN (STAGE_BYTES * 2)

// MODE 0: A from pre-split bf16 hi/lo planes (cp.async)
// MODE 1: A = relu(Anode[p>>3] + rel[p]·W0c) computed on the fly (W1 fusion)
template <int MODE>
__global__ __launch_bounds__(256, 2)
void gemm_mma(const __nv_bfloat16* __restrict__ Ahi,
              const __nv_bfloat16* __restrict__ Alo,
              const __nv_bfloat16* __restrict__ Bhi,
              const __nv_bfloat16* __restrict__ Blo,
              const float* __restrict__ bias, const float* __restrict__ Cin,
              const float* __restrict__ Anode, const float* __restrict__ rel,
              const float* __restrict__ W0c3,
              float* __restrict__ OutF,
              __nv_bfloat16* __restrict__ OutHi, __nv_bfloat16* __restrict__ OutLo,
              int M, int K, int Np, int realN, int ldc, int doRelu)
{
    extern __shared__ __align__(128) char smem[];
    const uint32_t sb = smem_u32(smem);
    const int tid = threadIdx.x, lane = tid & 31, wid = tid >> 5;
    const int warpM = (wid & 1) * 64;
    const int warpN = (wid >> 1) * 32;
    const long m0 = (long)blockIdx.y * 128;
    const int  n0 = blockIdx.x * 128;
    const int  nc = K >> 5;

    // cp.async: B always; A only in MODE 0
    auto issue_chunk = [&](int c) {
        const uint32_t st = sb + (uint32_t)(c & 1) * STAGE_BYTES;
        const int k0 = c << 5;
        if (MODE == 0) {
#pragma unroll
            for (int t = 0; t < 4; t++) {
                const int gi = tid + t * 256;
                const int pl = gi >> 9, idx = gi & 511;
                const int row = idx >> 2, q = idx & 3;
                const long gm = m0 + row;
                const __nv_bfloat16* src =
                    (pl ? Alo : Ahi) + (gm < M ? gm : 0) * (long)K + k0 + q * 8;
                const uint32_t dst = st + (pl ? SA_LO : SA_HI) + row * ASTRIDE + q * 16;
                cp16(dst, src, gm < M ? 16 : 0);
            }
        }
#pragma unroll
        for (int t = 0; t < 4; t++) {
            const int gi = tid + t * 256;
            const int pl = gi >> 9, idx = gi & 511;
            const int row = idx >> 4, q = idx & 15;
            const __nv_bfloat16* src =
                (pl ? Blo : Bhi) + (long)(k0 + row) * Np + n0 + q * 8;
            const uint32_t dst = st + (pl ? SB_LO : SB_HI) + row * BSTRIDE + q * 16;
            cp16(dst, src, 16);
        }
    };

    // MODE 1: per-thread row set and rel triplets (rows (tid>>3)+32t, col block tid&7)
    float r0[4], r1[4], r2[4];
    if (MODE == 1) {
#pragma unroll
        for (int t = 0; t < 4; t++) {
            const long p = m0 + (tid >> 3) + 32 * t;
            r0[t] = rel[p * 3 + 0];
            r1[t] = rel[p * 3 + 1];
            r2[t] = rel[p * 3 + 2];
        }
    }

    float acc[4][4][4];
#pragma unroll
    for (int i = 0; i < 4; i++)
#pragma unroll
        for (int j = 0; j < 4; j++)
#pragma unroll
            for (int r = 0; r < 4; r++) acc[i][j][r] = 0.f;

    const uint32_t aOff = (uint32_t)((warpM + (lane & 15)) * ASTRIDE + ((lane >> 4) << 4));
    const uint32_t bOff = (uint32_t)(((lane & 7) + ((lane >> 3) & 1) * 8) * BSTRIDE +
                                     (warpN + ((lane >> 4) << 3)) * 2);

    issue_chunk(0);
    cp_commit();

    for (int c = 0; c < nc; c++) {
        const uint32_t st = sb + (uint32_t)(c & 1) * STAGE_BYTES;

        __syncthreads();                  // MMAs of c-1 complete everywhere
        if (c + 1 < nc) issue_chunk(c + 1);
        cp_commit();

        if (MODE == 1) {
            // build A(c) = split(relu(Anode + rel·W0c)) directly in SMEM
            const int c4 = tid & 7;
            const int k0 = c << 5;
            const float4 w0 = *(const float4*)(W0c3 + 0   + k0 + c4 * 4);
            const float4 w1 = *(const float4*)(W0c3 + 256 + k0 + c4 * 4);
            const float4 w2 = *(const float4*)(W0c3 + 512 + k0 + c4 * 4);
#pragma unroll
            for (int t = 0; t < 4; t++) {
                const int row = (tid >> 3) + 32 * t;
                const long node = (m0 + row) >> 3;
                const float4 a = *(const float4*)(Anode + node * 256 + k0 + c4 * 4);
                float4 o;
                o.x = fmaxf(a.x + r0[t] * w0.x + r1[t] * w1.x + r2[t] * w2.x, 0.f);
                o.y = fmaxf(a.y + r0[t] * w0.y + r1[t] * w1.y + r2[t] * w2.y, 0.f);
                o.z = fmaxf(a.z + r0[t] * w0.z + r1[t] * w1.z + r2[t] * w2.z, 0.f);
                o.w = fmaxf(a.w + r0[t] * w0.w + r1[t] * w1.w + r2[t] * w2.w, 0.f);
                const __nv_bfloat16 hx = __float2bfloat16(o.x), hy = __float2bfloat16(o.y);
                const __nv_bfloat16 hz = __float2bfloat16(o.z), hw = __float2bfloat16(o.w);
                uint2 hp, lp;
                hp.x = pack2(hx, hy); hp.y = pack2(hz, hw);
                lp.x = pack2(__float2bfloat16(o.x - __bfloat162float(hx)),
                             __float2bfloat16(o.y - __bfloat162float(hy)));
                lp.y = pack2(__float2bfloat16(o.z - __bfloat162float(hz)),
                             __float2bfloat16(o.w - __bfloat162float(hw)));
                const int off = row * ASTRIDE + c4 * 8;
                *(uint2*)(smem + (st - sb) + SA_HI + off) = hp;
                *(uint2*)(smem + (st - sb) + SA_LO + off) = lp;
            }
        }

        cp_wait1();                       // chunk c's cp.async data arrived
        __syncthreads();                  // ...and is visible to all threads

        const uint32_t aAddr = st + aOff;
        const uint32_t bAddr = st + SB_HI + bOff;

#pragma unroll
        for (int ks = 0; ks < 2; ks++) {
            uint32_t ah[4][4], bh[8], bl[8];
#pragma unroll
            for (int mi = 0; mi < 4; mi++)
                ldm_x4(ah[mi], aAddr + SA_HI + (uint32_t)(mi * 16 * ASTRIDE + ks * 32));
#pragma unroll
            for (int j = 0; j < 2; j++) {
                const uint32_t bo = bAddr + (uint32_t)(ks * 16 * BSTRIDE + j * 32);
                ldm_x4t(bh + j * 4, bo);
                ldm_x4t(bl + j * 4, bo + (SB_LO - SB_HI));
            }
#pragma unroll
            for (int mi = 0; mi < 4; mi++)
#pragma unroll
                for (int nj = 0; nj < 4; nj++) {
                    mma16816(acc[mi][nj], ah[mi], bh + nj * 2);
                    mma16816(acc[mi][nj], ah[mi], bl + nj * 2);
                }
            // lo(A) x hi(B) — load al after ah products to cap register pressure
            uint32_t al[4][4];
#pragma unroll
            for (int mi = 0; mi < 4; mi++)
                ldm_x4(al[mi], aAddr + SA_LO + (uint32_t)(mi * 16 * ASTRIDE + ks * 32));
#pragma unroll
            for (int mi = 0; mi < 4; mi++)
#pragma unroll
                for (int nj = 0; nj < 4; nj++)
                    mma16816(acc[mi][nj], al[mi], bh + nj * 2);
        }
    }

    // ---- epilogue ----
    const long gmBase = m0 + warpM + (lane >> 2);
    const int  gcBase = n0 + warpN + (lane & 3) * 2;
#pragma unroll
    for (int mi = 0; mi < 4; mi++) {
#pragma unroll
        for (int half = 0; half < 2; half++) {
            const long gr = gmBase + mi * 16 + half * 8;
            if (gr >= M) continue;
#pragma unroll
            for (int nj = 0; nj < 4; nj++) {
                const int gc = gcBase + nj * 8;
                if (gc >= realN) continue;
                float vx = acc[mi][nj][half * 2 + 0];
                float vy = acc[mi][nj][half * 2 + 1];
                if (bias) { vx += bias[gc]; vy += bias[gc + 1]; }
                if (Cin) {
                    const float2 cv = *(const float2*)(Cin + gr * (long)ldc + gc);
                    vx += cv.x; vy += cv.y;
                }
                if (doRelu) { vx = fmaxf(vx, 0.f); vy = fmaxf(vy, 0.f); }
                if (OutHi) {
                    const __nv_bfloat16 hx = __float2bfloat16(vx);
                    const __nv_bfloat16 hy = __float2bfloat16(vy);
                    *(uint32_t*)(OutHi + gr * (long)ldc + gc) = pack2(hx, hy);
                    *(uint32_t*)(OutLo + gr * (long)ldc + gc) =
                        pack2(__float2bfloat16(vx - __bfloat162float(hx)),
                              __float2bfloat16(vy - __bfloat162float(hy)));
                } else {
                    float2 o; o.x = vx; o.y = vy;
                    *(float2*)(OutF + gr * (long)ldc + gc) = o;
                }
            }
        }
    }
}

// ---------------------------------------------------------------------------
__global__ __launch_bounds__(256)
void prep_weight(const float* __restrict__ W, __nv_bfloat16* __restrict__ hi,
                 __nv_bfloat16* __restrict__ lo, int K, int N, int Kpad, int Npad)
{
    const int i = blockIdx.x * blockDim.x + threadIdx.x;
    if (i >= Kpad * Npad) return;
    const int k = i / Npad, n = i % Npad;
    const float v = (k < K && n < N) ? W[(long)k * N + n] : 0.f;
    const __nv_bfloat16 h = __float2bfloat16(v);
    hi[i] = h;
    lo[i] = __float2bfloat16(v - __bfloat162float(h));
}

__global__ __launch_bounds__(256)
void split_x(const float* __restrict__ X, __nv_bfloat16* __restrict__ hi,
             __nv_bfloat16* __restrict__ lo)
{
    const long i = (long)blockIdx.x * blockDim.x + threadIdx.x;
    if (i >= (long)N_NODES * 64) return;
    const float4 v = *(const float4*)(X + i * 4);
    const __nv_bfloat16 hx = __float2bfloat16(v.x), hy = __float2bfloat16(v.y);
    const __nv_bfloat16 hz = __float2bfloat16(v.z), hw = __float2bfloat16(v.w);
    uint2 hp, lp;
    hp.x = pack2(hx, hy); hp.y = pack2(hz, hw);
    lp.x = pack2(__float2bfloat16(v.x - __bfloat162float(hx)),
                 __float2bfloat16(v.y - __bfloat162float(hy)));
    lp.y = pack2(__float2bfloat16(v.z - __bfloat162float(hz)),
                 __float2bfloat16(v.w - __bfloat162float(hw)));
    *(uint2*)(hi + i * 4) = hp;
    *(uint2*)(lo + i * 4) = lp;
}

__global__ __launch_bounds__(256)
void cluster_kernel(float* __restrict__ out)
{
    const int i = blockIdx.x * blockDim.x + threadIdx.x;
    if (i < M_PTS) out[i] = (float)(i >> 3);
}

// ---------------------------------------------------------------------------
extern "C" void kernel_launch(void* const* d_in, const int* in_sizes, int n_in,
                              void* d_out, int out_size)
{
    const float* X    = (const float*)d_in[0];
    const float* Wg0  = (const float*)d_in[1];
    const float* bg0  = (const float*)d_in[2];
    const float* Wg1  = (const float*)d_in[3];
    const float* bg1  = (const float*)d_in[4];
    const float* Wg2  = (const float*)d_in[5];
    const float* bg2  = (const float*)d_in[6];
    const float* Wdec = (const float*)d_in[7];
    const float* bdec = (const float*)d_in[8];
    const float* W0   = (const float*)d_in[9];
    const float* b0   = (const float*)d_in[10];
    const float* W1   = (const float*)d_in[11];
    const float* b1   = (const float*)d_in[12];
    const float* W2   = (const float*)d_in[13];
    const float* b2   = (const float*)d_in[14];

    float* out = (float*)d_out;
    float* out_rel     = out;
    float* out_decoded = out + 1200000;
    float* out_cluster = out + 1200000 + 102400000;

    float *T, *Abuf;
    __nv_bfloat16 *whi, *wlo, *xhi, *xlo, *h1hi, *h1lo, *h2hi, *h2lo;
    __nv_bfloat16 *fhi, *flo, *p1hi, *p1lo;
    cudaGetSymbolAddress((void**)&T,    g_T);
    cudaGetSymbolAddress((void**)&Abuf, g_A);
    cudaGetSymbolAddress((void**)&whi,  g_whi);
    cudaGetSymbolAddress((void**)&wlo,  g_wlo);
    cudaGetSymbolAddress((void**)&xhi,  g_xhi);
    cudaGetSymbolAddress((void**)&xlo,  g_xlo);
    cudaGetSymbolAddress((void**)&h1hi, g_h1hi);
    cudaGetSymbolAddress((void**)&h1lo, g_h1lo);
    cudaGetSymbolAddress((void**)&h2hi, g_h2hi);
    cudaGetSymbolAddress((void**)&h2lo, g_h2lo);
    cudaGetSymbolAddress((void**)&fhi,  g_fhi);
    cudaGetSymbolAddress((void**)&flo,  g_flo);
    cudaGetSymbolAddress((void**)&p1hi, g_p1hi);
    cudaGetSymbolAddress((void**)&p1lo, g_p1lo);

    cudaFuncSetAttribute(gemm_mma<0>, cudaFuncAttributeMaxDynamicSharedMemorySize, SMEM_DYN);
    cudaFuncSetAttribute(gemm_mma<1>, cudaFuncAttributeMaxDynamicSharedMemorySize, SMEM_DYN);

    const float* W0a = W0;
    const float* W0b = W0 + 256 * 256;
    const float* W0c = W0 + 320 * 256;

    auto prep = [&](const float* W, int off, int K, int N, int Kp, int Np) {
        const int total = Kp * Np;
        prep_weight<<<(total + 255) / 256, 256>>>(W, whi + off, wlo + off, K, N, Kp, Np);
    };
    prep(Wg0,  OFF_WG0,  256, 256, 256, 256);
    prep(Wg1,  OFF_WG1,  256, 128, 256, 128);
    prep(Wg2,  OFF_WG2,  128,  64, 128, 128);
    prep(Wdec, OFF_WDEC,  64,  24,  64, 128);
    prep(W0a,  OFF_W0A,  256, 256, 256, 256);
    prep(W0b,  OFF_W0B,   64, 256,  64, 256);
    prep(W1,   OFF_W1,   256, 256, 256, 256);
    prep(W2,   OFF_W2,   256, 256, 256, 256);

    split_x<<<(N_NODES * 64 + 255) / 256, 256>>>(X, xhi, xlo);

    auto gemm0 = [&](const __nv_bfloat16* Ahi, const __nv_bfloat16* Alo, int off,
                     const float* bias, const float* Cin,
                     float* OutF, __nv_bfloat16* OutHi, __nv_bfloat16* OutLo,
                     int M, int K, int Np, int realN, int ldc, int relu) {
        dim3 grid((realN + 127) / 128, (M + 127) / 128);
        gemm_mma<0><<<grid, 256, SMEM_DYN>>>(Ahi, Alo, whi + off, wlo + off, bias, Cin,
                                             nullptr, nullptr, nullptr,
                                             OutF, OutHi, OutLo, M, K, Np, realN, ldc, relu);
    };

    // global MLP
    gemm0(xhi,  xlo,  OFF_WG0, bg0, nullptr, nullptr, h1hi, h1lo, N_NODES, 256, 256, 256, 256, 1);
    gemm0(h1hi, h1lo, OFF_WG1, bg1, nullptr, nullptr, h2hi, h2lo, N_NODES, 256, 128, 128, 128, 1);
    gemm0(h2hi, h2lo, OFF_WG2, bg2, nullptr, nullptr, fhi,  flo,  N_NODES, 128, 128,  64,  64, 1);
    // decoder head -> relative_points (fp32 into d_out)
    gemm0(fhi, flo, OFF_WDEC, bdec, nullptr, out_rel, nullptr, nullptr, N_NODES, 64, 128, 24, 24, 0);
    // node-level shared part of point-MLP layer 0 (fp32)
    gemm0(xhi, xlo, OFF_W0A, b0,      nullptr, T,    nullptr, nullptr, N_NODES, 256, 256, 256, 256, 0);
    gemm0(fhi, flo, OFF_W0B, nullptr, T,       Abuf, nullptr, nullptr, N_NODES,  64, 256, 256, 256, 0);
    // point-MLP layer 1 with fused h0 construction (MODE 1)
    {
        dim3 grid(2, M_PTS / 128);
        gemm_mma<1><<<grid, 256, SMEM_DYN>>>(nullptr, nullptr, whi + OFF_W1, wlo + OFF_W1,
                                             b1, nullptr, Abuf, out_rel, W0c,
                                             nullptr, p1hi, p1lo,
                                             M_PTS, 256, 256, 256, 256, 1);
    }
    // point-MLP layer 2 -> decoded output (fp32)
    gemm0(p1hi, p1lo, OFF_W2, b2, nullptr, out_decoded, nullptr, nullptr, M_PTS, 256, 256, 256, 256, 1);
    // cluster ids
    cluster_kernel<<<(M_PTS + 255) / 256, 256>>>(out_cluster);
}